// round 14
// baseline (speedup 1.0000x reference)
#include <cuda_runtime.h>
#include <cuda_fp16.h>
#include <cstdint>

#define DD 128
#define TT 64
#define NPOW 9           // A^0 .. A^8 (Taylor K=8; tail ~1e-5 relative)
#define BB 8192

// ---------------- device scratch (no allocs allowed) ----------------
// g_Bf[t] holds P_t TRANSPOSED: [n][k] n-major (prep writes coalesced,
// GEMM consumes via non-trans ldmatrix).
__device__ __align__(1024) __half g_Bf[TT][DD * DD];

// ---------------- helpers ----------------
__device__ __forceinline__ uint32_t smem_u32(const void* p) {
    uint32_t a;
    asm("{ .reg .u64 t; cvta.to.shared.u64 t, %1; cvt.u32.u64 %0, t; }" : "=r"(a) : "l"(p));
    return a;
}
__device__ __forceinline__ void ldsm4(uint32_t* r, uint32_t a) {
    asm volatile("ldmatrix.sync.aligned.m8n8.x4.shared.b16 {%0,%1,%2,%3}, [%4];"
                 : "=r"(r[0]), "=r"(r[1]), "=r"(r[2]), "=r"(r[3]) : "r"(a));
}
__device__ __forceinline__ void mma16816(float* d, const uint32_t* a,
                                         uint32_t b0, uint32_t b1) {
    asm volatile(
        "mma.sync.aligned.m16n8k16.row.col.f32.f16.f16.f32 "
        "{%0,%1,%2,%3}, {%4,%5,%6,%7}, {%8,%9}, {%0,%1,%2,%3};"
        : "+f"(d[0]), "+f"(d[1]), "+f"(d[2]), "+f"(d[3])
        : "r"(a[0]), "r"(a[1]), "r"(a[2]), "r"(a[3]), "r"(b0), "r"(b1));
}
__device__ __forceinline__ void cp16(uint32_t dst, const void* src) {
    asm volatile("cp.async.cg.shared.global [%0], [%1], 16;" :: "r"(dst), "l"(src));
}

// ---------------- prologue: 32 CTAs, powers-by-columns + combine -----------
// CTA b owns P columns n0..n0+3 = Pt rows n0..n0+3 -> coalesced stores.
#define A_PAD 132
#define PREP_SMEM (128 * A_PAD * 4 + NPOW * 128 * 4 * 4)   // 86016

__global__ void __launch_bounds__(256, 1)
prep_all_kernel(const float* __restrict__ W) {
    extern __shared__ float sm[];
    int tid = threadIdx.x, bid = blockIdx.x;

    float* Arow = sm;                    // [i][132]: A[i][j] = dt*W[i][j]
    float* Mk = sm + 128 * A_PAD;        // [k][j][4]

#pragma unroll
    for (int it = 0; it < 64; it++) {
        int idx = it * 256 + tid;
        int r = idx >> 7, c = idx & 127;
        Arow[r * A_PAD + c] = 0.01f * W[idx];
    }
    __syncthreads();

    int i = tid & 127, cp = tid >> 7;    // row i of P; cols c0=2cp, c0+1
    int n0 = bid * 4, c0 = 2 * cp;

    float m[NPOW][2];                    // M_k[i][c0], M_k[i][c1]
    m[0][0] = (i == n0 + c0) ? 1.0f : 0.0f;
    m[0][1] = (i == n0 + c0 + 1) ? 1.0f : 0.0f;
    m[1][0] = Arow[i * A_PAD + n0 + c0];
    m[1][1] = Arow[i * A_PAD + n0 + c0 + 1];
    *(float2*)&Mk[1 * 512 + i * 4 + c0] = make_float2(m[1][0], m[1][1]);
    __syncthreads();

    for (int k = 2; k < NPOW; k++) {
        const float* Mp = Mk + (k - 1) * 512;
        const float* ar = Arow + i * A_PAD;
        float s0 = 0.0f, s1 = 0.0f;
#pragma unroll
        for (int j = 0; j < 128; j += 4) {
            float4 a = *(const float4*)(ar + j);
            float2 p0 = *(const float2*)(Mp + (j + 0) * 4 + c0);
            float2 p1 = *(const float2*)(Mp + (j + 1) * 4 + c0);
            float2 p2 = *(const float2*)(Mp + (j + 2) * 4 + c0);
            float2 p3 = *(const float2*)(Mp + (j + 3) * 4 + c0);
            s0 += a.x * p0.x; s1 += a.x * p0.y;
            s0 += a.y * p1.x; s1 += a.y * p1.y;
            s0 += a.z * p2.x; s1 += a.z * p2.y;
            s0 += a.w * p3.x; s1 += a.w * p3.y;
        }
        m[k][0] = s0; m[k][1] = s1;
        *(float2*)&Mk[k * 512 + i * 4 + c0] = make_float2(s0, s1);
        __syncthreads();
    }

    // combine from registers, store transposed (coalesced along i)
    for (int t = 0; t < TT; t++) {
        float tf = (float)t, c = 1.0f, s0 = 0.0f, s1 = 0.0f;
#pragma unroll
        for (int k = 0; k < NPOW; k++) {
            s0 += c * m[k][0];
            s1 += c * m[k][1];
            c *= tf / (float)(k + 1);
        }
        g_Bf[t][(n0 + c0) * DD + i]     = __float2half_rn(s0);
        g_Bf[t][(n0 + c0 + 1) * DD + i] = __float2half_rn(s1);
    }
}

// ---------------- main GEMM: t-batched, double-buffered B ----------------
// A loaded straight from fp32 x with inline fp16 conversion (no g_xh).
// B tile is Pt [n][k] n-major: consumed via non-trans ldmatrix.
#define TC 2
#define A_STRIDE 272            // bytes: 128 fp16 + 8 pad
#define SM_A 0
#define SM_B0 (SM_A + 128 * A_STRIDE)         // 34816
#define SM_B1 (SM_B0 + 128 * A_STRIDE)        // 69632
#define SM_TOTAL (SM_B1 + 128 * A_STRIDE)     // 104448

__global__ void __launch_bounds__(256, 2)
gemm_kernel(const float* __restrict__ x, float* __restrict__ out) {
    extern __shared__ __align__(16) char smem[];
    int tid = threadIdx.x;
    int rb = blockIdx.x, t0 = blockIdx.y * TC;

    const float* xg = x + (size_t)rb * 128 * DD;
    uint32_t sb = smem_u32(smem);

    // B[t0] first so cp.async overlaps the A convert
#pragma unroll
    for (int j = 0; j < 8; j++) {
        int idx = j * 256 + tid;
        int r = idx >> 4, cc = idx & 15;
        cp16(sb + SM_B0 + r * A_STRIDE + cc * 16, g_Bf[t0] + r * DD + cc * 8);
    }
    asm volatile("cp.async.commit_group;" ::: "memory");

    // A: fp32 -> fp16 inline (rounding identical to old prep path)
#pragma unroll
    for (int j = 0; j < 16; j++) {
        int idx = j * 256 + tid;            // 4096 chunks of 4 elems
        int row = idx >> 5, c = idx & 31;   // 32 chunks per row
        float4 v = *(const float4*)(xg + row * DD + c * 4);
        __half2 h0 = __floats2half2_rn(v.x, v.y);
        __half2 h1 = __floats2half2_rn(v.z, v.w);
        *(uint2*)(smem + SM_A + row * A_STRIDE + c * 8) =
            make_uint2(*(uint32_t*)&h0, *(uint32_t*)&h1);
    }

    int wid = tid >> 5, lane = tid & 31;
    int wm = wid & 3, wn = wid >> 2;
    uint32_t offA = (uint32_t)((wm * 32 + (lane & 15)) * A_STRIDE + (lane >> 4) * 16);
    // non-trans B fragment on [n][k] tile:
    uint32_t offB = (uint32_t)((wn * 64 + (lane & 7) + ((lane >> 1) & 8)) * A_STRIDE +
                               (lane & 8) * 2);
    uint32_t Ab = sb + SM_A + offA;
    uint32_t Bbuf[2] = {sb + SM_B0 + offB, sb + SM_B1 + offB};
    uint32_t Braw[2] = {sb + SM_B0, sb + SM_B1};

    int g = lane >> 2, q = lane & 3;
    size_t rowbase = (size_t)rb * 128 + wm * 32;

#pragma unroll
    for (int tt = 0; tt < TC; tt++) {
        if (tt < TC - 1) {
            const __half* Bn = g_Bf[t0 + tt + 1];
            uint32_t dst = Braw[(tt + 1) & 1];
#pragma unroll
            for (int j = 0; j < 8; j++) {
                int idx = j * 256 + tid;
                int r = idx >> 4, cc = idx & 15;
                cp16(dst + r * A_STRIDE + cc * 16, Bn + r * DD + cc * 8);
            }
            asm volatile("cp.async.commit_group;" ::: "memory");
            asm volatile("cp.async.wait_group 1;" ::: "memory");
        } else {
            asm volatile("cp.async.wait_group 0;" ::: "memory");
        }
        __syncthreads();

        uint32_t Bb = Bbuf[tt & 1];
        float acc[2][8][4];
#pragma unroll
        for (int i = 0; i < 2; i++)
#pragma unroll
            for (int j = 0; j < 8; j++)
#pragma unroll
                for (int k = 0; k < 4; k++) acc[i][j][k] = 0.0f;

#pragma unroll
        for (int ks = 0; ks < 8; ks++) {
            uint32_t a0[4], a1[4];
            ldsm4(a0, Ab + ks * 32);
            ldsm4(a1, Ab + ks * 32 + 16 * A_STRIDE);
#pragma unroll
            for (int j = 0; j < 4; j++) {    // n-groups of 16
                uint32_t b[4];
                ldsm4(b, Bb + j * 16 * A_STRIDE + ks * 32);
                mma16816(acc[0][2 * j],     a0, b[0], b[1]);
                mma16816(acc[0][2 * j + 1], a0, b[2], b[3]);
                mma16816(acc[1][2 * j],     a1, b[0], b[1]);
                mma16816(acc[1][2 * j + 1], a1, b[2], b[3]);
            }
        }

        int t = t0 + tt;
#pragma unroll
        for (int mt = 0; mt < 2; mt++) {
            size_t row = rowbase + mt * 16 + g;
#pragma unroll
            for (int nb = 0; nb < 8; nb++) {
                int col = wn * 64 + nb * 8 + q * 2;
                float* o = out + (row * TT + t) * DD + col;
                *(float2*)o = make_float2(acc[mt][nb][0], acc[mt][nb][1]);
                *(float2*)(o + (size_t)8 * TT * DD) = make_float2(acc[mt][nb][2], acc[mt][nb][3]);
            }
        }
        __syncthreads();
    }
}

// ---------------- launch ----------------
extern "C" void kernel_launch(void* const* d_in, const int* in_sizes, int n_in,
                              void* d_out, int out_size) {
    const float* x = (const float*)d_in[0];
    const float* W = (const float*)d_in[1];
    float* out = (float*)d_out;

    cudaFuncSetAttribute(prep_all_kernel, cudaFuncAttributeMaxDynamicSharedMemorySize, PREP_SMEM);
    prep_all_kernel<<<32, 256, PREP_SMEM>>>(W);

    cudaFuncSetAttribute(gemm_kernel, cudaFuncAttributeMaxDynamicSharedMemorySize, SM_TOTAL);
    gemm_kernel<<<dim3(BB / 128, TT / TC), 256, SM_TOTAL>>>(x, out);
}

// round 15
// speedup vs baseline: 1.0383x; 1.0383x over previous
#include <cuda_runtime.h>
#include <cuda_fp16.h>
#include <cstdint>

#define DD 128
#define TT 64
#define NPOW 9           // A^0 .. A^8 (Taylor K=8; tail ~1e-5 relative)
#define BB 8192

// ---------------- device scratch (no allocs allowed) ----------------
// g_Bf[t] holds P_t TRANSPOSED: [n][k] n-major (prep writes coalesced,
// GEMM consumes via non-trans ldmatrix).
__device__ __align__(1024) __half g_Bf[TT][DD * DD];
__device__ __align__(1024) __half g_xh[BB * DD];        // x fp16

// ---------------- helpers ----------------
__device__ __forceinline__ uint32_t smem_u32(const void* p) {
    uint32_t a;
    asm("{ .reg .u64 t; cvta.to.shared.u64 t, %1; cvt.u32.u64 %0, t; }" : "=r"(a) : "l"(p));
    return a;
}
__device__ __forceinline__ void ldsm4(uint32_t* r, uint32_t a) {
    asm volatile("ldmatrix.sync.aligned.m8n8.x4.shared.b16 {%0,%1,%2,%3}, [%4];"
                 : "=r"(r[0]), "=r"(r[1]), "=r"(r[2]), "=r"(r[3]) : "r"(a));
}
__device__ __forceinline__ void mma16816(float* d, const uint32_t* a,
                                         uint32_t b0, uint32_t b1) {
    asm volatile(
        "mma.sync.aligned.m16n8k16.row.col.f32.f16.f16.f32 "
        "{%0,%1,%2,%3}, {%4,%5,%6,%7}, {%8,%9}, {%0,%1,%2,%3};"
        : "+f"(d[0]), "+f"(d[1]), "+f"(d[2]), "+f"(d[3])
        : "r"(a[0]), "r"(a[1]), "r"(a[2]), "r"(a[3]), "r"(b0), "r"(b1));
}
__device__ __forceinline__ void cp16(uint32_t dst, const void* src) {
    asm volatile("cp.async.cg.shared.global [%0], [%1], 16;" :: "r"(dst), "l"(src));
}

// ---------------- fused prologue: ONE launch --------------------------------
// CTAs [0,64):   powers-by-columns + combine, 2 P-columns per CTA (halved
//                serial work vs 4-col version).  Coalesced transposed stores.
// CTAs [64,192): x fp32 -> fp16 conversion (8192 elements each).
#define A_PAD 132
#define PREP_SMEM (128 * A_PAD * 4 + NPOW * 128 * 2 * 4)   // 67584 + 9216 = 76800

__global__ void __launch_bounds__(256, 1)
prep_all_kernel(const float* __restrict__ x, const float* __restrict__ W) {
    extern __shared__ float sm[];
    int tid = threadIdx.x, bid = blockIdx.x;

    if (bid < 64) {
        float* Arow = sm;                    // [i][132]: A[i][j] = dt*W[i][j]
        float* Mk = sm + 128 * A_PAD;        // [k][j][2]

#pragma unroll
        for (int it = 0; it < 64; it++) {
            int idx = it * 256 + tid;
            int r = idx >> 7, c = idx & 127;
            Arow[r * A_PAD + c] = 0.01f * W[idx];
        }
        __syncthreads();

        int i = tid & 127, c = tid >> 7;     // row i; column-select 0/1
        int col = bid * 2 + c;               // owned P column

        float m[NPOW];                       // M_k[i][col] register-resident
        m[0] = (i == col) ? 1.0f : 0.0f;
        m[1] = Arow[i * A_PAD + col];
        Mk[1 * 256 + i * 2 + c] = m[1];
        __syncthreads();

        for (int k = 2; k < NPOW; k++) {
            const float* Mp = Mk + (k - 1) * 256;
            const float* ar = Arow + i * A_PAD;
            float s = 0.0f;
#pragma unroll
            for (int j = 0; j < 128; j += 4) {
                float4 a = *(const float4*)(ar + j);
                s += a.x * Mp[(j + 0) * 2 + c];
                s += a.y * Mp[(j + 1) * 2 + c];
                s += a.z * Mp[(j + 2) * 2 + c];
                s += a.w * Mp[(j + 3) * 2 + c];
            }
            m[k] = s;
            Mk[k * 256 + i * 2 + c] = s;
            __syncthreads();
        }

        // combine from registers, store transposed (coalesced along i)
        for (int t = 0; t < TT; t++) {
            float tf = (float)t, cc = 1.0f, s = 0.0f;
#pragma unroll
            for (int k = 0; k < NPOW; k++) {
                s += cc * m[k];
                cc *= tf / (float)(k + 1);
            }
            g_Bf[t][col * DD + i] = __float2half_rn(s);
        }
    } else {
        int cb = bid - 64;
        const float4* xs = (const float4*)(x + (size_t)cb * 8192);
        uint2* dst = (uint2*)(g_xh + (size_t)cb * 8192);
#pragma unroll
        for (int j = 0; j < 8; j++) {
            float4 v = xs[j * 256 + tid];
            __half2 h0 = __floats2half2_rn(v.x, v.y);
            __half2 h1 = __floats2half2_rn(v.z, v.w);
            dst[j * 256 + tid] = make_uint2(*(uint32_t*)&h0, *(uint32_t*)&h1);
        }
    }
}

// ---------------- main GEMM: t-batched, double-buffered B (R13, proven) ----
// B tile is Pt [n][k] n-major: consumed via NON-trans ldmatrix.
#define TC 2
#define A_STRIDE 272            // bytes: 128 fp16 + 8 pad
#define SM_A 0
#define SM_B0 (SM_A + 128 * A_STRIDE)         // 34816
#define SM_B1 (SM_B0 + 128 * A_STRIDE)        // 69632
#define SM_TOTAL (SM_B1 + 128 * A_STRIDE)     // 104448

__global__ void __launch_bounds__(256, 2)
gemm_kernel(float* __restrict__ out) {
    extern __shared__ __align__(16) char smem[];
    int tid = threadIdx.x;
    int rb = blockIdx.x, t0 = blockIdx.y * TC;

    const __half* Ah = g_xh + (size_t)rb * 128 * DD;
    uint32_t sb = smem_u32(smem);

#pragma unroll
    for (int j = 0; j < 8; j++) {
        int idx = j * 256 + tid;
        int row = idx >> 4, c = idx & 15;
        *(float4*)(smem + SM_A + row * A_STRIDE + c * 16) =
            *(const float4*)(Ah + row * DD + c * 8);
    }
#pragma unroll
    for (int j = 0; j < 8; j++) {
        int idx = j * 256 + tid;
        int r = idx >> 4, cc = idx & 15;
        cp16(sb + SM_B0 + r * A_STRIDE + cc * 16, g_Bf[t0] + r * DD + cc * 8);
    }
    asm volatile("cp.async.commit_group;" ::: "memory");

    int wid = tid >> 5, lane = tid & 31;
    int wm = wid & 3, wn = wid >> 2;
    uint32_t offA = (uint32_t)((wm * 32 + (lane & 15)) * A_STRIDE + (lane >> 4) * 16);
    // non-trans B fragment on [n][k] tile
    uint32_t offB = (uint32_t)((wn * 64 + (lane & 7) + ((lane >> 1) & 8)) * A_STRIDE +
                               (lane & 8) * 2);
    uint32_t Ab = sb + SM_A + offA;
    uint32_t Bbuf[2] = {sb + SM_B0 + offB, sb + SM_B1 + offB};
    uint32_t Braw[2] = {sb + SM_B0, sb + SM_B1};

    int g = lane >> 2, q = lane & 3;
    size_t rowbase = (size_t)rb * 128 + wm * 32;

#pragma unroll
    for (int tt = 0; tt < TC; tt++) {
        if (tt < TC - 1) {
            const __half* Bn = g_Bf[t0 + tt + 1];
            uint32_t dst = Braw[(tt + 1) & 1];
#pragma unroll
            for (int j = 0; j < 8; j++) {
                int idx = j * 256 + tid;
                int r = idx >> 4, cc = idx & 15;
                cp16(dst + r * A_STRIDE + cc * 16, Bn + r * DD + cc * 8);
            }
            asm volatile("cp.async.commit_group;" ::: "memory");
            asm volatile("cp.async.wait_group 1;" ::: "memory");
        } else {
            asm volatile("cp.async.wait_group 0;" ::: "memory");
        }
        __syncthreads();

        uint32_t Bb = Bbuf[tt & 1];
        float acc[2][8][4];
#pragma unroll
        for (int i = 0; i < 2; i++)
#pragma unroll
            for (int j = 0; j < 8; j++)
#pragma unroll
                for (int k = 0; k < 4; k++) acc[i][j][k] = 0.0f;

#pragma unroll
        for (int ks = 0; ks < 8; ks++) {
            uint32_t a0[4], a1[4];
            ldsm4(a0, Ab + ks * 32);
            ldsm4(a1, Ab + ks * 32 + 16 * A_STRIDE);
#pragma unroll
            for (int j = 0; j < 4; j++) {    // n-groups of 16
                uint32_t b[4];
                ldsm4(b, Bb + j * 16 * A_STRIDE + ks * 32);
                mma16816(acc[0][2 * j],     a0, b[0], b[1]);
                mma16816(acc[0][2 * j + 1], a0, b[2], b[3]);
                mma16816(acc[1][2 * j],     a1, b[0], b[1]);
                mma16816(acc[1][2 * j + 1], a1, b[2], b[3]);
            }
        }

        int t = t0 + tt;
#pragma unroll
        for (int mt = 0; mt < 2; mt++) {
            size_t row = rowbase + mt * 16 + g;
#pragma unroll
            for (int nb = 0; nb < 8; nb++) {
                int col = wn * 64 + nb * 8 + q * 2;
                float* o = out + (row * TT + t) * DD + col;
                *(float2*)o = make_float2(acc[mt][nb][0], acc[mt][nb][1]);
                *(float2*)(o + (size_t)8 * TT * DD) = make_float2(acc[mt][nb][2], acc[mt][nb][3]);
            }
        }
        __syncthreads();
    }
}

// ---------------- launch ----------------
extern "C" void kernel_launch(void* const* d_in, const int* in_sizes, int n_in,
                              void* d_out, int out_size) {
    const float* x = (const float*)d_in[0];
    const float* W = (const float*)d_in[1];
    float* out = (float*)d_out;

    cudaFuncSetAttribute(prep_all_kernel, cudaFuncAttributeMaxDynamicSharedMemorySize, PREP_SMEM);
    prep_all_kernel<<<192, 256, PREP_SMEM>>>(x, W);

    cudaFuncSetAttribute(gemm_kernel, cudaFuncAttributeMaxDynamicSharedMemorySize, SM_TOTAL);
    gemm_kernel<<<dim3(BB / 128, TT / TC), 256, SM_TOTAL>>>(out);
}

// round 16
// speedup vs baseline: 1.1582x; 1.1156x over previous
#include <cuda_runtime.h>
#include <cuda_fp16.h>
#include <cstdint>

#define DD 128
#define TT 64
#define NPOW 9           // A^0 .. A^8 (Taylor K=8; tail ~1e-5 relative)
#define BB 8192

// ---------------- device scratch (no allocs allowed) ----------------
// g_Bf[t] holds P_t TRANSPOSED: [n][k] n-major.
__device__ __align__(1024) __half g_Bf[TT][DD * DD];
__device__ __align__(1024) __half g_xh[BB * DD];        // x fp16

// ---------------- helpers ----------------
__device__ __forceinline__ uint32_t smem_u32(const void* p) {
    uint32_t a;
    asm("{ .reg .u64 t; cvta.to.shared.u64 t, %1; cvt.u32.u64 %0, t; }" : "=r"(a) : "l"(p));
    return a;
}
__device__ __forceinline__ void ldsm4(uint32_t* r, uint32_t a) {
    asm volatile("ldmatrix.sync.aligned.m8n8.x4.shared.b16 {%0,%1,%2,%3}, [%4];"
                 : "=r"(r[0]), "=r"(r[1]), "=r"(r[2]), "=r"(r[3]) : "r"(a));
}
__device__ __forceinline__ void mma16816(float* d, const uint32_t* a,
                                         uint32_t b0, uint32_t b1) {
    asm volatile(
        "mma.sync.aligned.m16n8k16.row.col.f32.f16.f16.f32 "
        "{%0,%1,%2,%3}, {%4,%5,%6,%7}, {%8,%9}, {%0,%1,%2,%3};"
        : "+f"(d[0]), "+f"(d[1]), "+f"(d[2]), "+f"(d[3])
        : "r"(a[0]), "r"(a[1]), "r"(a[2]), "r"(a[3]), "r"(b0), "r"(b1));
}
__device__ __forceinline__ void cp16(uint32_t dst, const void* src) {
    asm volatile("cp.async.cg.shared.global [%0], [%1], 16;" :: "r"(dst), "l"(src));
}
__device__ __forceinline__ void stcs2(float* p, float a, float b) {
    asm volatile("st.global.cs.v2.f32 [%0], {%1, %2};" :: "l"(p), "f"(a), "f"(b) : "memory");
}

// ---------------- fused prologue: ONE launch --------------------------------
// CTAs [0,128):   powers, 1 P-column per CTA, 2 threads per row (half-dots).
// CTAs [128,256): x fp32 -> fp16 conversion (8192 elements each).
#define A_PAD 132
#define PREP_SMEM (128 * A_PAD * 4 + NPOW * 128 * 4 + 256 * 4)  // 67584+4608+1024

__global__ void __launch_bounds__(256, 1)
prep_all_kernel(const float* __restrict__ x, const float* __restrict__ W) {
    extern __shared__ float sm[];
    int tid = threadIdx.x, bid = blockIdx.x;

    if (bid < 128) {
        float* Arow = sm;                        // [i][132]
        float* Mk = sm + 128 * A_PAD;            // [k][128]
        float* part = Mk + NPOW * 128;           // [128][2]

#pragma unroll
        for (int it = 0; it < 64; it++) {
            int idx = it * 256 + tid;
            int r = idx >> 7, c = idx & 127;
            Arow[r * A_PAD + c] = 0.01f * W[idx];
        }
        __syncthreads();

        int i = tid & 127, h = tid >> 7;         // row i, half h
        int col = bid;

        float m[NPOW];                           // full M_k[i][col] in both halves
        m[0] = (i == col) ? 1.0f : 0.0f;
        m[1] = Arow[i * A_PAD + col];
        if (h == 0) Mk[1 * 128 + i] = m[1];
        __syncthreads();

        for (int k = 2; k < NPOW; k++) {
            const float* Mp = Mk + (k - 1) * 128;
            const float* ar = Arow + i * A_PAD + h * 64;
            const float* mp = Mp + h * 64;
            float s = 0.0f;
#pragma unroll
            for (int j = 0; j < 64; j += 4) {
                float4 a = *(const float4*)(ar + j);
                s += a.x * mp[j + 0];
                s += a.y * mp[j + 1];
                s += a.z * mp[j + 2];
                s += a.w * mp[j + 3];
            }
            part[i * 2 + h] = s;
            __syncthreads();
            m[k] = part[i * 2] + part[i * 2 + 1];
            if (h == 0) Mk[k * 128 + i] = m[k];
            __syncthreads();
        }

        // combine: halves split the t-range 32/32; coalesced along i
        int tbeg = h * 32, tend = tbeg + 32;
        for (int t = tbeg; t < tend; t++) {
            float tf = (float)t, cc = 1.0f, s = 0.0f;
#pragma unroll
            for (int k = 0; k < NPOW; k++) {
                s += cc * m[k];
                cc *= tf / (float)(k + 1);
            }
            g_Bf[t][col * DD + i] = __float2half_rn(s);
        }
    } else {
        int cb = bid - 128;
        const float4* xs = (const float4*)(x + (size_t)cb * 8192);
        uint2* dst = (uint2*)(g_xh + (size_t)cb * 8192);
#pragma unroll
        for (int j = 0; j < 8; j++) {
            float4 v = xs[j * 256 + tid];
            __half2 h0 = __floats2half2_rn(v.x, v.y);
            __half2 h1 = __floats2half2_rn(v.z, v.w);
            dst[j * 256 + tid] = make_uint2(*(uint32_t*)&h0, *(uint32_t*)&h1);
        }
    }
}

// ---------------- main GEMM: t-batched, double-buffered B ----------------
// A and B[t0] via cp.async; B tile is Pt [n][k]: non-trans ldmatrix; stores .cs
#define TC 2
#define A_STRIDE 272            // bytes: 128 fp16 + 8 pad
#define SM_A 0
#define SM_B0 (SM_A + 128 * A_STRIDE)         // 34816
#define SM_B1 (SM_B0 + 128 * A_STRIDE)        // 69632
#define SM_TOTAL (SM_B1 + 128 * A_STRIDE)     // 104448

__global__ void __launch_bounds__(256, 2)
gemm_kernel(float* __restrict__ out) {
    extern __shared__ __align__(16) char smem[];
    int tid = threadIdx.x;
    int rb = blockIdx.x, t0 = blockIdx.y * TC;

    const __half* Ah = g_xh + (size_t)rb * 128 * DD;
    uint32_t sb = smem_u32(smem);

    // A tile + B[t0] in one cp.async group
#pragma unroll
    for (int j = 0; j < 8; j++) {
        int idx = j * 256 + tid;
        int r = idx >> 4, cc = idx & 15;
        cp16(sb + SM_A + r * A_STRIDE + cc * 16, Ah + r * DD + cc * 8);
        cp16(sb + SM_B0 + r * A_STRIDE + cc * 16, g_Bf[t0] + r * DD + cc * 8);
    }
    asm volatile("cp.async.commit_group;" ::: "memory");

    int wid = tid >> 5, lane = tid & 31;
    int wm = wid & 3, wn = wid >> 2;
    uint32_t offA = (uint32_t)((wm * 32 + (lane & 15)) * A_STRIDE + (lane >> 4) * 16);
    uint32_t offB = (uint32_t)((wn * 64 + (lane & 7) + ((lane >> 1) & 8)) * A_STRIDE +
                               (lane & 8) * 2);
    uint32_t Ab = sb + SM_A + offA;
    uint32_t Bbuf[2] = {sb + SM_B0 + offB, sb + SM_B1 + offB};
    uint32_t Braw[2] = {sb + SM_B0, sb + SM_B1};

    int g = lane >> 2, q = lane & 3;
    size_t rowbase = (size_t)rb * 128 + wm * 32;

#pragma unroll
    for (int tt = 0; tt < TC; tt++) {
        if (tt < TC - 1) {
            const __half* Bn = g_Bf[t0 + tt + 1];
            uint32_t dst = Braw[(tt + 1) & 1];
#pragma unroll
            for (int j = 0; j < 8; j++) {
                int idx = j * 256 + tid;
                int r = idx >> 4, cc = idx & 15;
                cp16(dst + r * A_STRIDE + cc * 16, Bn + r * DD + cc * 8);
            }
            asm volatile("cp.async.commit_group;" ::: "memory");
            asm volatile("cp.async.wait_group 1;" ::: "memory");
        } else {
            asm volatile("cp.async.wait_group 0;" ::: "memory");
        }
        __syncthreads();

        uint32_t Bb = Bbuf[tt & 1];
        float acc[2][8][4];
#pragma unroll
        for (int i = 0; i < 2; i++)
#pragma unroll
            for (int j = 0; j < 8; j++)
#pragma unroll
                for (int k = 0; k < 4; k++) acc[i][j][k] = 0.0f;

#pragma unroll
        for (int ks = 0; ks < 8; ks++) {
            uint32_t a0[4], a1[4];
            ldsm4(a0, Ab + ks * 32);
            ldsm4(a1, Ab + ks * 32 + 16 * A_STRIDE);
#pragma unroll
            for (int j = 0; j < 4; j++) {    // n-groups of 16
                uint32_t b[4];
                ldsm4(b, Bb + j * 16 * A_STRIDE + ks * 32);
                mma16816(acc[0][2 * j],     a0, b[0], b[1]);
                mma16816(acc[0][2 * j + 1], a0, b[2], b[3]);
                mma16816(acc[1][2 * j],     a1, b[0], b[1]);
                mma16816(acc[1][2 * j + 1], a1, b[2], b[3]);
            }
        }

        int t = t0 + tt;
#pragma unroll
        for (int mt = 0; mt < 2; mt++) {
            size_t row = rowbase + mt * 16 + g;
#pragma unroll
            for (int nb = 0; nb < 8; nb++) {
                int col = wn * 64 + nb * 8 + q * 2;
                float* o = out + (row * TT + t) * DD + col;
                stcs2(o, acc[mt][nb][0], acc[mt][nb][1]);
                stcs2(o + (size_t)8 * TT * DD, acc[mt][nb][2], acc[mt][nb][3]);
            }
        }
        __syncthreads();
    }
}

// ---------------- launch ----------------
extern "C" void kernel_launch(void* const* d_in, const int* in_sizes, int n_in,
                              void* d_out, int out_size) {
    const float* x = (const float*)d_in[0];
    const float* W = (const float*)d_in[1];
    float* out = (float*)d_out;

    cudaFuncSetAttribute(prep_all_kernel, cudaFuncAttributeMaxDynamicSharedMemorySize, PREP_SMEM);
    prep_all_kernel<<<256, 256, PREP_SMEM>>>(x, W);

    cudaFuncSetAttribute(gemm_kernel, cudaFuncAttributeMaxDynamicSharedMemorySize, SM_TOTAL);
    gemm_kernel<<<dim3(BB / 128, TT / TC), 256, SM_TOTAL>>>(out);
}